// round 13
// baseline (speedup 1.0000x reference)
#include <cuda_runtime.h>
#include <cuda_bf16.h>
#include <math.h>
#include <cstdint>

// Problem dims (fixed by the dataset)
#define Bc   8
#define Cc   512
#define Hc   96
#define Wc   144
#define HWc  (Hc * Wc)          // 13824
#define Ntok (Bc * HWc)         // 110592
#define Dd   512
#define Mm   512

// ---- GEMM tiling: CTA = 64 tok x 512 slots, 512 threads (16 warps) ----
// warp tile = 32 tok x 64 slots (balanced -> min ldmatrix bytes/MAC).
// K-chunk = 16 (bf16), 32 chunks, cp.async double buffer.
#define OFF_B     0
#define OFF_A     65536
#define OFF_CINV  73728
#define OFF_RSINV 75776
#define SMEM_DYN  76032

#define CP_ASYNC16(dst, src) \
    asm volatile("cp.async.ca.shared.global [%0], [%1], 16;" :: "r"(dst), "l"(src))
#define CP_COMMIT()  asm volatile("cp.async.commit_group;" ::: "memory")
#define CP_WAIT0()   asm volatile("cp.async.wait_group 0;" ::: "memory")

#define LDMX4(r, addr) \
    asm volatile("ldmatrix.sync.aligned.m8n8.x4.shared.b16 {%0,%1,%2,%3}, [%4];" \
        : "=r"((r)[0]), "=r"((r)[1]), "=r"((r)[2]), "=r"((r)[3]) : "r"(addr))

#define MMA16816(d, a, b0, b1) \
    asm volatile("mma.sync.aligned.m16n8k16.row.col.f32.bf16.bf16.f32 " \
        "{%0,%1,%2,%3}, {%4,%5,%6,%7}, {%8,%9}, {%0,%1,%2,%3};" \
        : "+f"((d)[0]), "+f"((d)[1]), "+f"((d)[2]), "+f"((d)[3]) \
        : "r"((a)[0]), "r"((a)[1]), "r"((a)[2]), "r"((a)[3]), "r"(b0), "r"(b1))

__device__ __forceinline__ uint32_t smem_u32(const void* p) {
    uint32_t a;
    asm("{ .reg .u64 t; cvta.to.shared.u64 t, %1; cvt.u32.u64 %0, t; }"
        : "=r"(a) : "l"(p));
    return a;
}

// Scratch (allocation-free rule: __device__ globals)
__device__ __nv_bfloat16 g_qhi[(size_t)Ntok * Dd];
__device__ __nv_bfloat16 g_qlo[(size_t)Ntok * Dd];
__device__ __nv_bfloat16 g_memhi[Mm * Dd],  g_memlo[Mm * Dd];   // [m][k]
__device__ __nv_bfloat16 g_memThi[Dd * Mm], g_memTlo[Dd * Mm];  // [d][m]
__device__ float g_inv[Ntok];
__device__ float g_rowsum[Ntok];
__device__ float g_colsum[Mm];

// ---------------------------------------------------------------------------
// K1: per-token inverse L2 norm over channels; zero colsum (replay idempotency)
// ---------------------------------------------------------------------------
__global__ void k_norm(const float* __restrict__ x) {
    int n = blockIdx.x * 256 + threadIdx.x;
    if (blockIdx.x == 0) {
        g_colsum[threadIdx.x]       = 0.0f;
        g_colsum[threadIdx.x + 256] = 0.0f;
    }
    if (n >= Ntok) return;
    int b = n / HWc, hw = n % HWc;
    const float* p = x + (size_t)b * Cc * HWc + hw;
    float s = 0.0f;
#pragma unroll 8
    for (int c = 0; c < Cc; c++) {
        float v = p[(size_t)c * HWc];
        s += v * v;
    }
    g_inv[n] = 1.0f / fmaxf(sqrtf(s), 1e-12f);
}

// ---------------------------------------------------------------------------
// K2: bf16 hi/lo split of memory, [m][k] and transposed [d][m]
// ---------------------------------------------------------------------------
__global__ void k_prep(const float* __restrict__ pmem) {
    int idx = blockIdx.x * 256 + threadIdx.x;   // 1024 blocks -> 262144
    int m = idx >> 9, d = idx & 511;
    float v = pmem[idx];
    __nv_bfloat16 h = __float2bfloat16(v);
    __nv_bfloat16 l = __float2bfloat16(v - __bfloat162float(h));
    g_memhi[idx] = h;           g_memlo[idx] = l;
    g_memThi[d * 512 + m] = h;  g_memTlo[d * 512 + m] = l;
}

// ---------------------------------------------------------------------------
// K3: transpose+normalize q -> bf16 hi/lo [N,D]
// ---------------------------------------------------------------------------
__global__ void k_qt(const float* __restrict__ x) {
    __shared__ float tile[32][33];
    int b   = blockIdx.z;
    int hw0 = blockIdx.x * 32;
    int d0  = blockIdx.y * 32;
    for (int r = threadIdx.y; r < 32; r += 8)
        tile[r][threadIdx.x] =
            x[((size_t)(b * Cc + d0 + r)) * HWc + hw0 + threadIdx.x];
    __syncthreads();
    for (int r = threadIdx.y; r < 32; r += 8) {
        int n = b * HWc + hw0 + r;
        float v = tile[threadIdx.x][r] * g_inv[n];
        __nv_bfloat16 h = __float2bfloat16(v);
        size_t off = (size_t)n * Dd + d0 + threadIdx.x;
        g_qhi[off] = h;
        g_qlo[off] = __float2bfloat16(v - __bfloat162float(h));
    }
}

// ---------------------------------------------------------------------------
// Staging: B tile (512 rows x 16 k, hi+lo) via cp.async, panel layout
// ---------------------------------------------------------------------------
__device__ __forceinline__ void stage_B(uint32_t sb, int buf,
                                        const __nv_bfloat16* __restrict__ Bhi,
                                        const __nv_bfloat16* __restrict__ Blo,
                                        int kc, int tid) {
#pragma unroll
    for (int it = 0; it < 4; it++) {
        int idx = tid + it * 512;          // 0..2047
        int hl = idx >> 10;
        int n  = (idx >> 1) & 511;
        int p  = idx & 1;
        const __nv_bfloat16* src = (hl ? Blo : Bhi) + (size_t)n * 512 + kc * 16 + p * 8;
        uint32_t dst = sb + OFF_B + buf * 32768 + hl * 16384 + p * 8192 + n * 16;
        CP_ASYNC16(dst, src);
    }
}

// A tile (64 rows x 16 k, hi+lo) via cp.async (gemm1)
__device__ __forceinline__ void stage_A1(uint32_t sb, int buf,
                                         const __nv_bfloat16* __restrict__ Ahi,
                                         const __nv_bfloat16* __restrict__ Alo,
                                         int n0, int kc, int tid) {
    if (tid < 256) {
        int hl = tid >> 7;
        int r  = (tid >> 1) & 63;
        int p  = tid & 1;
        const __nv_bfloat16* src = (hl ? Alo : Ahi) + (size_t)(n0 + r) * 512 + kc * 16 + p * 8;
        uint32_t dst = sb + OFF_A + buf * 4096 + hl * 2048 + p * 1024 + r * 16;
        CP_ASYNC16(dst, src);
    }
}

// A tile for gemm2: read raw E (f32), convert to bf16 hi/lo, and in passing
// emit out_sm = E*rinv, out_sq = E*cinv (each E element touched exactly once).
__device__ __forceinline__ void stage_A2(char* dyn, int buf,
                                         float* __restrict__ E,
                                         float* __restrict__ out_sm,
                                         const float* rs_inv, const float* cinv_s,
                                         int n0, int kc, int tid) {
    int r  = tid >> 3;
    int kk = (tid & 7) * 2;
    size_t off = (size_t)(n0 + r) * 512 + kc * 16 + kk;
    float2 e2 = *(const float2*)&E[off];
    float ri = rs_inv[r];
    *(float2*)&out_sm[off] = make_float2(e2.x * ri, e2.y * ri);
    int cgl = kc * 16 + kk;
    *(float2*)&E[off] = make_float2(e2.x * cinv_s[cgl], e2.y * cinv_s[cgl + 1]);
    __nv_bfloat16 h0 = __float2bfloat16(e2.x), h1 = __float2bfloat16(e2.y);
    __nv_bfloat16 l0 = __float2bfloat16(e2.x - __bfloat162float(h0));
    __nv_bfloat16 l1 = __float2bfloat16(e2.y - __bfloat162float(h1));
    int p = kk >> 3, c = kk & 7;
    char* d0 = dyn + OFF_A + buf * 4096 + p * 1024 + r * 16 + c * 2;
    *(__nv_bfloat162*)d0          = __halves2bfloat162(h0, h1);
    *(__nv_bfloat162*)(d0 + 2048) = __halves2bfloat162(l0, l1);
}

// ---------------------------------------------------------------------------
// One K-chunk: warp tile 32 tok x 64 slots.
// 12 ldmatrix.x4 (4 A + 8 B, was 18) + 48 mma (error-compensated bf16x3).
// acc[mi*8 + 2*jp+h] = (rows mi*16..+15, slots sgp*64 + jp*16 + h*8 ..+7)
// ---------------------------------------------------------------------------
__device__ __forceinline__ void chunk_compute(uint32_t sb, int buf, int tg,
                                              int sgp, int lane,
                                              float acc[16][4]) {
    uint32_t ah[2][4], al[2][4];
#pragma unroll
    for (int mi = 0; mi < 2; mi++) {
        uint32_t a_addr = sb + OFF_A + buf * 4096 + (lane >> 4) * 1024
                        + (tg * 32 + mi * 16 + (lane & 15)) * 16;
        LDMX4(ah[mi], a_addr);
        LDMX4(al[mi], a_addr + 2048);
    }

    int g = lane >> 3;
    uint32_t b_off = (uint32_t)((g & 1) * 8192 + ((g >> 1) * 8 + (lane & 7)) * 16);
    uint32_t b_hi = sb + OFF_B + buf * 32768 + b_off;
#pragma unroll
    for (int jp = 0; jp < 4; jp++) {
        uint32_t nb = (uint32_t)((sgp * 64 + jp * 16) * 16);
        uint32_t bh[4], bl[4];
        LDMX4(bh, b_hi + nb);
        LDMX4(bl, b_hi + 16384 + nb);
#pragma unroll
        for (int mi = 0; mi < 2; mi++) {
            MMA16816(acc[mi * 8 + 2 * jp],     ah[mi], bh[0], bh[1]);
            MMA16816(acc[mi * 8 + 2 * jp],     ah[mi], bl[0], bl[1]);
            MMA16816(acc[mi * 8 + 2 * jp],     al[mi], bh[0], bh[1]);
            MMA16816(acc[mi * 8 + 2 * jp + 1], ah[mi], bh[2], bh[3]);
            MMA16816(acc[mi * 8 + 2 * jp + 1], ah[mi], bl[2], bl[3]);
            MMA16816(acc[mi * 8 + 2 * jp + 1], al[mi], bh[2], bh[3]);
        }
    }
}

// ---------------------------------------------------------------------------
// K4: GEMM1 -> out_sq = E = exp(q . mem^T)   (raw, unnormalized)
// ---------------------------------------------------------------------------
__global__ void __launch_bounds__(512, 1)
k_g1(float* __restrict__ out_sq) {
    extern __shared__ char dyn[];
    uint32_t sb = smem_u32(dyn);
    int tid = threadIdx.x, lane = tid & 31, wid = tid >> 5;
    int tg = wid & 1, sgp = wid >> 1;
    int n0 = blockIdx.x * 64;

    float acc[16][4];
#pragma unroll
    for (int j = 0; j < 16; j++)
#pragma unroll
        for (int q = 0; q < 4; q++) acc[j][q] = 0.0f;

    stage_B(sb, 0, g_memhi, g_memlo, 0, tid);
    stage_A1(sb, 0, g_qhi, g_qlo, n0, 0, tid);
    CP_COMMIT(); CP_WAIT0(); __syncthreads();

    int buf = 0;
    for (int kc = 0; kc < 32; kc++) {
        if (kc < 31) {
            stage_B(sb, buf ^ 1, g_memhi, g_memlo, kc + 1, tid);
            stage_A1(sb, buf ^ 1, g_qhi, g_qlo, n0, kc + 1, tid);
            CP_COMMIT();
        }
        chunk_compute(sb, buf, tg, sgp, lane, acc);
        if (kc < 31) CP_WAIT0();
        __syncthreads();
        buf ^= 1;
    }

    // epilogue: E = exp(score) (|score|<=1: no max-sub)
    int row0 = n0 + tg * 32 + (lane >> 2);
#pragma unroll
    for (int mi = 0; mi < 2; mi++)
#pragma unroll
        for (int j = 0; j < 8; j++) {
            int col = sgp * 64 + j * 8 + (lane & 3) * 2;
            const float* a = acc[mi * 8 + j];
            *(float2*)&out_sq[(size_t)(row0 + mi * 16) * 512 + col] =
                make_float2(__expf(a[0]), __expf(a[1]));
            *(float2*)&out_sq[(size_t)(row0 + mi * 16 + 8) * 512 + col] =
                make_float2(__expf(a[2]), __expf(a[3]));
        }
}

// ---------------------------------------------------------------------------
// K5: stream E once -> per-token rowsums (exact) + colsum atomics
// ---------------------------------------------------------------------------
__global__ void __launch_bounds__(256)
k_sums(const float* __restrict__ E) {
    __shared__ float rp[64];
    int tid = threadIdx.x, lane = tid & 31, w = tid >> 5;
    int n0 = blockIdx.x * 64;
    if (tid < 64) rp[tid] = 0.0f;
    __syncthreads();

    int c0 = w * 64 + lane * 2;
    float cs0 = 0.0f, cs1 = 0.0f;
    for (int t = 0; t < 64; t++) {
        float2 v = *(const float2*)&E[(size_t)(n0 + t) * 512 + c0];
        cs0 += v.x; cs1 += v.y;
        float s = v.x + v.y;
#pragma unroll
        for (int off = 16; off; off >>= 1)
            s += __shfl_xor_sync(0xFFFFFFFFu, s, off);
        if (lane == 0) atomicAdd(&rp[t], s);
    }
    __syncthreads();
    if (tid < 64) g_rowsum[n0 + tid] = rp[tid];
    atomicAdd(&g_colsum[c0],     cs0);
    atomicAdd(&g_colsum[c0 + 1], cs1);
}

// ---------------------------------------------------------------------------
// K6: GEMM2 upd = (E*rinv) . mem, fused score finalization in A-staging.
// Output written in [B, D, H, W] layout via smem transpose chunks.
// ---------------------------------------------------------------------------
__global__ void __launch_bounds__(512, 1)
k_g2(float* __restrict__ out_sq,       // raw E in, E*cinv out
     float* __restrict__ out_sm,
     float* __restrict__ out_upd) {
    extern __shared__ char dyn[];
    uint32_t sb = smem_u32(dyn);
    float* cinv_s = (float*)(dyn + OFF_CINV);
    float* rs_inv = (float*)(dyn + OFF_RSINV);
    int tid = threadIdx.x, lane = tid & 31, wid = tid >> 5;
    int tg = wid & 1, sgp = wid >> 1;
    int n0 = blockIdx.x * 64;

    cinv_s[tid] = 1.0f / g_colsum[tid];
    if (tid < 64) rs_inv[tid] = 1.0f / g_rowsum[n0 + tid];
    __syncthreads();

    float acc[16][4];
#pragma unroll
    for (int j = 0; j < 16; j++)
#pragma unroll
        for (int q = 0; q < 4; q++) acc[j][q] = 0.0f;

    stage_B(sb, 0, g_memThi, g_memTlo, 0, tid);
    CP_COMMIT();
    stage_A2(dyn, 0, out_sq, out_sm, rs_inv, cinv_s, n0, 0, tid);
    CP_WAIT0(); __syncthreads();

    int buf = 0;
    for (int kc = 0; kc < 32; kc++) {
        if (kc < 31) {
            stage_B(sb, buf ^ 1, g_memThi, g_memTlo, kc + 1, tid);
            CP_COMMIT();
            stage_A2(dyn, buf ^ 1, out_sq, out_sm, rs_inv, cinv_s, n0, kc + 1, tid);
        }
        chunk_compute(sb, buf, tg, sgp, lane, acc);
        if (kc < 31) CP_WAIT0();
        __syncthreads();
        buf ^= 1;
    }

    // scale rows by rinv (upd = P.mem with P = E*rinv)
    {
#pragma unroll
        for (int mi = 0; mi < 2; mi++) {
            float r0 = rs_inv[tg * 32 + mi * 16 + (lane >> 2)];
            float r1 = rs_inv[tg * 32 + mi * 16 + (lane >> 2) + 8];
#pragma unroll
            for (int j = 0; j < 8; j++) {
                acc[mi * 8 + j][0] *= r0; acc[mi * 8 + j][1] *= r0;
                acc[mi * 8 + j][2] *= r1; acc[mi * 8 + j][3] *= r1;
            }
        }
    }

    // transpose to [B, D, H, W] in 16 chunks of 32 d-values
    float* sT = (float*)dyn;                  // reuse B region: [32][68]
    int b   = n0 / HWc;
    int hw0 = n0 % HWc;
    for (int ci = 0; ci < 16; ci++) {
        if (sgp == (ci >> 1)) {
            int jp0 = (ci & 1) * 4;
#pragma unroll
            for (int jj = 0; jj < 4; jj++) {
                int dl = jj * 8 + (lane & 3) * 2;
#pragma unroll
                for (int mi = 0; mi < 2; mi++) {
                    int t = tg * 32 + mi * 16 + (lane >> 2);
                    const float* a = acc[mi * 8 + jp0 + jj];
                    sT[dl * 68 + t]           = a[0];
                    sT[(dl + 1) * 68 + t]     = a[1];
                    sT[dl * 68 + t + 8]       = a[2];
                    sT[(dl + 1) * 68 + t + 8] = a[3];
                }
            }
        }
        __syncthreads();
        {
            int dl  = tid >> 4;
            int hwl = (tid & 15) * 4;
            int d   = ci * 32 + dl;
            float4 v = make_float4(sT[dl * 68 + hwl],     sT[dl * 68 + hwl + 1],
                                   sT[dl * 68 + hwl + 2], sT[dl * 68 + hwl + 3]);
            *(float4*)&out_upd[((size_t)(b * Dd + d)) * HWc + hw0 + hwl] = v;
        }
        __syncthreads();
    }
}

// ---------------------------------------------------------------------------
extern "C" void kernel_launch(void* const* d_in, const int* in_sizes, int n_in,
                              void* d_out, int out_size) {
    const float* x    = (const float*)d_in[0];   // query_source [8,512,96,144]
    const float* pmem = (const float*)d_in[1];   // memory [512,512]
    float* out = (float*)d_out;

    const size_t ND = (size_t)Ntok * Dd;         // 56,623,104
    float* out_upd = out;                        // [B, D, H, W]
    float* out_sq  = out + ND;                   // softmax over tokens [N, M]
    float* out_sm  = out + 2 * ND;               // softmax over slots  [N, M]

    // Idempotent, capture-safe; needed for >48KB dynamic smem
    cudaFuncSetAttribute(k_g1, cudaFuncAttributeMaxDynamicSharedMemorySize, SMEM_DYN);
    cudaFuncSetAttribute(k_g2, cudaFuncAttributeMaxDynamicSharedMemorySize, SMEM_DYN);

    k_norm<<<Ntok / 256, 256>>>(x);
    k_prep<<<(Mm * Dd) / 256, 256>>>(pmem);
    k_qt<<<dim3(HWc / 32, Dd / 32, Bc), dim3(32, 8)>>>(x);
    k_g1<<<Ntok / 64, 512, SMEM_DYN>>>(out_sq);
    k_sums<<<Ntok / 64, 256>>>(out_sq);
    k_g2<<<Ntok / 64, 512, SMEM_DYN>>>(out_sq, out_sm, out_upd);
    (void)in_sizes; (void)n_in; (void)out_size;
}

// round 14
// speedup vs baseline: 1.3831x; 1.3831x over previous
#include <cuda_runtime.h>
#include <cuda_bf16.h>
#include <math.h>
#include <cstdint>

// Problem dims (fixed by the dataset)
#define Bc   8
#define Cc   512
#define Hc   96
#define Wc   144
#define HWc  (Hc * Wc)          // 13824
#define Ntok (Bc * HWc)         // 110592
#define Dd   512
#define Mm   512

// ---- k_g1 smem layout: BK=32 (2 sub-panels of 16k), double buffered ----
// B panel (16k): 2hl x 2p x 512 rows x 16B = 32768 B;  4 panels (buf*2+sub)
// A panel (16k): 2hl x 2p x  64 rows x 16B = 4096 B;   4 panels
#define G1_OFF_B  0
#define G1_OFF_A  131072
#define G1_SMEM   147456

// ---- k_g2 smem layout (R12-exact) ----
#define G2_OFF_B     0
#define G2_OFF_A     65536
#define G2_OFF_CINV  73728
#define G2_OFF_RSINV 75776
#define G2_SMEM      76032

#define CP_ASYNC16(dst, src) \
    asm volatile("cp.async.ca.shared.global [%0], [%1], 16;" :: "r"(dst), "l"(src))
#define CP_COMMIT()  asm volatile("cp.async.commit_group;" ::: "memory")
#define CP_WAIT0()   asm volatile("cp.async.wait_group 0;" ::: "memory")

#define LDMX4(r, addr) \
    asm volatile("ldmatrix.sync.aligned.m8n8.x4.shared.b16 {%0,%1,%2,%3}, [%4];" \
        : "=r"((r)[0]), "=r"((r)[1]), "=r"((r)[2]), "=r"((r)[3]) : "r"(addr))

#define MMA16816(d, a, b0, b1) \
    asm volatile("mma.sync.aligned.m16n8k16.row.col.f32.bf16.bf16.f32 " \
        "{%0,%1,%2,%3}, {%4,%5,%6,%7}, {%8,%9}, {%0,%1,%2,%3};" \
        : "+f"((d)[0]), "+f"((d)[1]), "+f"((d)[2]), "+f"((d)[3]) \
        : "r"((a)[0]), "r"((a)[1]), "r"((a)[2]), "r"((a)[3]), "r"(b0), "r"(b1))

__device__ __forceinline__ uint32_t smem_u32(const void* p) {
    uint32_t a;
    asm("{ .reg .u64 t; cvta.to.shared.u64 t, %1; cvt.u32.u64 %0, t; }"
        : "=r"(a) : "l"(p));
    return a;
}

// Scratch (allocation-free rule: __device__ globals)
__device__ __nv_bfloat16 g_qhi[(size_t)Ntok * Dd];
__device__ __nv_bfloat16 g_qlo[(size_t)Ntok * Dd];
__device__ __nv_bfloat16 g_memhi[Mm * Dd],  g_memlo[Mm * Dd];   // [m][k]
__device__ __nv_bfloat16 g_memThi[Dd * Mm], g_memTlo[Dd * Mm];  // [d][m]
__device__ float g_inv[Ntok];
__device__ float g_rowsum[Ntok];
__device__ float g_colsum[Mm];

// ---------------------------------------------------------------------------
// K1: per-token inverse L2 norm over channels; zero colsum (replay idempotency)
// ---------------------------------------------------------------------------
__global__ void k_norm(const float* __restrict__ x) {
    int n = blockIdx.x * 256 + threadIdx.x;
    if (blockIdx.x == 0) {
        g_colsum[threadIdx.x]       = 0.0f;
        g_colsum[threadIdx.x + 256] = 0.0f;
    }
    if (n >= Ntok) return;
    int b = n / HWc, hw = n % HWc;
    const float* p = x + (size_t)b * Cc * HWc + hw;
    float s = 0.0f;
#pragma unroll 8
    for (int c = 0; c < Cc; c++) {
        float v = p[(size_t)c * HWc];
        s += v * v;
    }
    g_inv[n] = 1.0f / fmaxf(sqrtf(s), 1e-12f);
}

// ---------------------------------------------------------------------------
// K2: bf16 hi/lo split of memory, [m][k] and transposed [d][m]
// ---------------------------------------------------------------------------
__global__ void k_prep(const float* __restrict__ pmem) {
    int idx = blockIdx.x * 256 + threadIdx.x;
    int m = idx >> 9, d = idx & 511;
    float v = pmem[idx];
    __nv_bfloat16 h = __float2bfloat16(v);
    __nv_bfloat16 l = __float2bfloat16(v - __bfloat162float(h));
    g_memhi[idx] = h;           g_memlo[idx] = l;
    g_memThi[d * 512 + m] = h;  g_memTlo[d * 512 + m] = l;
}

// ---------------------------------------------------------------------------
// K3: transpose+normalize q -> bf16 hi/lo [N,D]
// ---------------------------------------------------------------------------
__global__ void k_qt(const float* __restrict__ x) {
    __shared__ float tile[32][33];
    int b   = blockIdx.z;
    int hw0 = blockIdx.x * 32;
    int d0  = blockIdx.y * 32;
    for (int r = threadIdx.y; r < 32; r += 8)
        tile[r][threadIdx.x] =
            x[((size_t)(b * Cc + d0 + r)) * HWc + hw0 + threadIdx.x];
    __syncthreads();
    for (int r = threadIdx.y; r < 32; r += 8) {
        int n = b * HWc + hw0 + r;
        float v = tile[threadIdx.x][r] * g_inv[n];
        __nv_bfloat16 h = __float2bfloat16(v);
        size_t off = (size_t)n * Dd + d0 + threadIdx.x;
        g_qhi[off] = h;
        g_qlo[off] = __float2bfloat16(v - __bfloat162float(h));
    }
}

// ---------------------------------------------------------------------------
// Staging helpers (dstbase = absolute smem offset of the 16-k panel)
// ---------------------------------------------------------------------------
__device__ __forceinline__ void stage_B(uint32_t sb, uint32_t dstbase,
                                        const __nv_bfloat16* __restrict__ Bhi,
                                        const __nv_bfloat16* __restrict__ Blo,
                                        int kc, int tid) {
#pragma unroll
    for (int it = 0; it < 4; it++) {
        int idx = tid + it * 512;          // 0..2047
        int hl = idx >> 10;
        int n  = (idx >> 1) & 511;
        int p  = idx & 1;
        const __nv_bfloat16* src = (hl ? Blo : Bhi) + (size_t)n * 512 + kc * 16 + p * 8;
        uint32_t dst = sb + dstbase + hl * 16384 + p * 8192 + n * 16;
        CP_ASYNC16(dst, src);
    }
}

__device__ __forceinline__ void stage_A1(uint32_t sb, uint32_t dstbase,
                                         const __nv_bfloat16* __restrict__ Ahi,
                                         const __nv_bfloat16* __restrict__ Alo,
                                         int n0, int kc, int tid) {
    if (tid < 256) {
        int hl = tid >> 7;
        int r  = (tid >> 1) & 63;
        int p  = tid & 1;
        const __nv_bfloat16* src = (hl ? Alo : Ahi) + (size_t)(n0 + r) * 512 + kc * 16 + p * 8;
        uint32_t dst = sb + dstbase + hl * 2048 + p * 1024 + r * 16;
        CP_ASYNC16(dst, src);
    }
}

// A tile for gemm2: read raw E (f32), convert to bf16 hi/lo, and in passing
// emit out_sm = E*rinv, out_sq = E*cinv (each E element touched exactly once).
__device__ __forceinline__ void stage_A2(char* dyn, uint32_t dstbase,
                                         float* __restrict__ E,
                                         float* __restrict__ out_sm,
                                         const float* rs_inv, const float* cinv_s,
                                         int n0, int kc, int tid) {
    int r  = tid >> 3;
    int kk = (tid & 7) * 2;
    size_t off = (size_t)(n0 + r) * 512 + kc * 16 + kk;
    float2 e2 = *(const float2*)&E[off];
    float ri = rs_inv[r];
    *(float2*)&out_sm[off] = make_float2(e2.x * ri, e2.y * ri);
    int cgl = kc * 16 + kk;
    *(float2*)&E[off] = make_float2(e2.x * cinv_s[cgl], e2.y * cinv_s[cgl + 1]);
    __nv_bfloat16 h0 = __float2bfloat16(e2.x), h1 = __float2bfloat16(e2.y);
    __nv_bfloat16 l0 = __float2bfloat16(e2.x - __bfloat162float(h0));
    __nv_bfloat16 l1 = __float2bfloat16(e2.y - __bfloat162float(h1));
    int p = kk >> 3, c = kk & 7;
    char* d0 = dyn + dstbase + p * 1024 + r * 16 + c * 2;
    *(__nv_bfloat162*)d0          = __halves2bfloat162(h0, h1);
    *(__nv_bfloat162*)(d0 + 2048) = __halves2bfloat162(l0, l1);
}

// ---------------------------------------------------------------------------
// k_g1 chunk: warp tile 32 tok x 64 slots (4 A + 8 B ldmatrix.x4, 48 mma)
// ---------------------------------------------------------------------------
__device__ __forceinline__ void g1_chunk(uint32_t bbase, uint32_t abase,
                                         int tg, int sgp, int lane,
                                         float acc[16][4]) {
    uint32_t ah[2][4], al[2][4];
#pragma unroll
    for (int mi = 0; mi < 2; mi++) {
        uint32_t a_addr = abase + (lane >> 4) * 1024
                        + (tg * 32 + mi * 16 + (lane & 15)) * 16;
        LDMX4(ah[mi], a_addr);
        LDMX4(al[mi], a_addr + 2048);
    }
    int g = lane >> 3;
    uint32_t b_off = (uint32_t)((g & 1) * 8192 + ((g >> 1) * 8 + (lane & 7)) * 16);
    uint32_t b_hi = bbase + b_off;
#pragma unroll
    for (int jp = 0; jp < 4; jp++) {
        uint32_t nb = (uint32_t)((sgp * 64 + jp * 16) * 16);
        uint32_t bh[4], bl[4];
        LDMX4(bh, b_hi + nb);
        LDMX4(bl, b_hi + 16384 + nb);
#pragma unroll
        for (int mi = 0; mi < 2; mi++) {
            MMA16816(acc[mi * 8 + 2 * jp],     ah[mi], bh[0], bh[1]);
            MMA16816(acc[mi * 8 + 2 * jp],     ah[mi], bl[0], bl[1]);
            MMA16816(acc[mi * 8 + 2 * jp],     al[mi], bh[0], bh[1]);
            MMA16816(acc[mi * 8 + 2 * jp + 1], ah[mi], bh[2], bh[3]);
            MMA16816(acc[mi * 8 + 2 * jp + 1], ah[mi], bl[2], bl[3]);
            MMA16816(acc[mi * 8 + 2 * jp + 1], al[mi], bh[2], bh[3]);
        }
    }
}

// ---------------------------------------------------------------------------
// k_g2 chunk (R12-exact): warp tile 16 tok x 128 slots
// ---------------------------------------------------------------------------
__device__ __forceinline__ void g2_chunk(uint32_t sb, int buf, int tg,
                                         int sgp, int lane,
                                         float acc[16][4]) {
    uint32_t ah[4], al[4];
    uint32_t a_addr = sb + G2_OFF_A + buf * 4096 + (lane >> 4) * 1024
                    + (tg * 16 + (lane & 15)) * 16;
    LDMX4(ah, a_addr);
    LDMX4(al, a_addr + 2048);

    int g = lane >> 3;
    uint32_t b_off = (uint32_t)((g & 1) * 8192 + ((g >> 1) * 8 + (lane & 7)) * 16);
    uint32_t b_hi = sb + G2_OFF_B + buf * 32768 + b_off;
#pragma unroll
    for (int jp = 0; jp < 8; jp++) {
        uint32_t nb = (uint32_t)((sgp * 128 + jp * 16) * 16);
        uint32_t bh[4], bl[4];
        LDMX4(bh, b_hi + nb);
        LDMX4(bl, b_hi + 16384 + nb);
        MMA16816(acc[2 * jp],     ah, bh[0], bh[1]);
        MMA16816(acc[2 * jp],     ah, bl[0], bl[1]);
        MMA16816(acc[2 * jp],     al, bh[0], bh[1]);
        MMA16816(acc[2 * jp + 1], ah, bh[2], bh[3]);
        MMA16816(acc[2 * jp + 1], ah, bl[2], bl[3]);
        MMA16816(acc[2 * jp + 1], al, bh[2], bh[3]);
    }
}

// ---------------------------------------------------------------------------
// K4: GEMM1 -> out_sq = E = exp(q . mem^T)  (raw).  BK=32 per barrier.
// ---------------------------------------------------------------------------
__global__ void __launch_bounds__(512, 1)
k_g1(float* __restrict__ out_sq) {
    extern __shared__ char dyn[];
    uint32_t sb = smem_u32(dyn);
    int tid = threadIdx.x, lane = tid & 31, wid = tid >> 5;
    int tg = wid & 1, sgp = wid >> 1;
    int n0 = blockIdx.x * 64;

    float acc[16][4];
#pragma unroll
    for (int j = 0; j < 16; j++)
#pragma unroll
        for (int q = 0; q < 4; q++) acc[j][q] = 0.0f;

    // prologue: stage both 16-k sub-panels of stage 0
    stage_B(sb, G1_OFF_B + 0 * 32768, g_memhi, g_memlo, 0, tid);
    stage_B(sb, G1_OFF_B + 1 * 32768, g_memhi, g_memlo, 1, tid);
    stage_A1(sb, G1_OFF_A + 0 * 4096, g_qhi, g_qlo, n0, 0, tid);
    stage_A1(sb, G1_OFF_A + 1 * 4096, g_qhi, g_qlo, n0, 1, tid);
    CP_COMMIT(); CP_WAIT0(); __syncthreads();

    int buf = 0;
    for (int kc32 = 0; kc32 < 16; kc32++) {
        if (kc32 < 15) {
            int nb = buf ^ 1;
            int kc = (kc32 + 1) * 2;
            stage_B(sb, G1_OFF_B + (nb * 2 + 0) * 32768, g_memhi, g_memlo, kc, tid);
            stage_B(sb, G1_OFF_B + (nb * 2 + 1) * 32768, g_memhi, g_memlo, kc + 1, tid);
            stage_A1(sb, G1_OFF_A + (nb * 2 + 0) * 4096, g_qhi, g_qlo, n0, kc, tid);
            stage_A1(sb, G1_OFF_A + (nb * 2 + 1) * 4096, g_qhi, g_qlo, n0, kc + 1, tid);
            CP_COMMIT();
        }
        g1_chunk(sb + G1_OFF_B + (buf * 2 + 0) * 32768,
                 sb + G1_OFF_A + (buf * 2 + 0) * 4096, tg, sgp, lane, acc);
        g1_chunk(sb + G1_OFF_B + (buf * 2 + 1) * 32768,
                 sb + G1_OFF_A + (buf * 2 + 1) * 4096, tg, sgp, lane, acc);
        if (kc32 < 15) CP_WAIT0();
        __syncthreads();
        buf ^= 1;
    }

    // epilogue: E = exp(score) (|score|<=1: no max-sub)
    int row0 = n0 + tg * 32 + (lane >> 2);
#pragma unroll
    for (int mi = 0; mi < 2; mi++)
#pragma unroll
        for (int j = 0; j < 8; j++) {
            int col = sgp * 64 + j * 8 + (lane & 3) * 2;
            const float* a = acc[mi * 8 + j];
            *(float2*)&out_sq[(size_t)(row0 + mi * 16) * 512 + col] =
                make_float2(__expf(a[0]), __expf(a[1]));
            *(float2*)&out_sq[(size_t)(row0 + mi * 16 + 8) * 512 + col] =
                make_float2(__expf(a[2]), __expf(a[3]));
        }
}

// ---------------------------------------------------------------------------
// K5: stream E once -> per-token rowsums (exact) + colsum atomics
// ---------------------------------------------------------------------------
__global__ void __launch_bounds__(256)
k_sums(const float* __restrict__ E) {
    __shared__ float rp[64];
    int tid = threadIdx.x, lane = tid & 31, w = tid >> 5;
    int n0 = blockIdx.x * 64;
    if (tid < 64) rp[tid] = 0.0f;
    __syncthreads();

    int c0 = w * 64 + lane * 2;
    float cs0 = 0.0f, cs1 = 0.0f;
    for (int t = 0; t < 64; t++) {
        float2 v = *(const float2*)&E[(size_t)(n0 + t) * 512 + c0];
        cs0 += v.x; cs1 += v.y;
        float s = v.x + v.y;
#pragma unroll
        for (int off = 16; off; off >>= 1)
            s += __shfl_xor_sync(0xFFFFFFFFu, s, off);
        if (lane == 0) atomicAdd(&rp[t], s);
    }
    __syncthreads();
    if (tid < 64) g_rowsum[n0 + tid] = rp[tid];
    atomicAdd(&g_colsum[c0],     cs0);
    atomicAdd(&g_colsum[c0 + 1], cs1);
}

// ---------------------------------------------------------------------------
// K6: GEMM2 (R12-exact) upd = (E*rinv) . mem, fused score finalization.
// ---------------------------------------------------------------------------
__global__ void __launch_bounds__(512, 1)
k_g2(float* __restrict__ out_sq,       // raw E in, E*cinv out
     float* __restrict__ out_sm,
     float* __restrict__ out_upd) {
    extern __shared__ char dyn[];
    uint32_t sb = smem_u32(dyn);
    float* cinv_s = (float*)(dyn + G2_OFF_CINV);
    float* rs_inv = (float*)(dyn + G2_OFF_RSINV);
    int tid = threadIdx.x, lane = tid & 31, wid = tid >> 5;
    int tg = wid & 3, sgp = wid >> 2;
    int n0 = blockIdx.x * 64;

    cinv_s[tid] = 1.0f / g_colsum[tid];
    if (tid < 64) rs_inv[tid] = 1.0f / g_rowsum[n0 + tid];
    __syncthreads();

    float acc[16][4];
#pragma unroll
    for (int j = 0; j < 16; j++)
#pragma unroll
        for (int q = 0; q < 4; q++) acc[j][q] = 0.0f;

    stage_B(sb, G2_OFF_B, g_memThi, g_memTlo, 0, tid);
    CP_COMMIT();
    stage_A2(dyn, G2_OFF_A, out_sq, out_sm, rs_inv, cinv_s, n0, 0, tid);
    CP_WAIT0(); __syncthreads();

    int buf = 0;
    for (int kc = 0; kc < 32; kc++) {
        if (kc < 31) {
            stage_B(sb, G2_OFF_B + (buf ^ 1) * 32768, g_memThi, g_memTlo, kc + 1, tid);
            CP_COMMIT();
            stage_A2(dyn, G2_OFF_A + (buf ^ 1) * 4096, out_sq, out_sm,
                     rs_inv, cinv_s, n0, kc + 1, tid);
        }
        g2_chunk(sb, buf, tg, sgp, lane, acc);
        if (kc < 31) CP_WAIT0();
        __syncthreads();
        buf ^= 1;
    }

    // scale rows by rinv (upd = P.mem with P = E*rinv)
    {
        float r0 = rs_inv[tg * 16 + (lane >> 2)];
        float r1 = rs_inv[tg * 16 + (lane >> 2) + 8];
#pragma unroll
        for (int j = 0; j < 16; j++) {
            acc[j][0] *= r0; acc[j][1] *= r0;
            acc[j][2] *= r1; acc[j][3] *= r1;
        }
    }

    // transpose to [B, D, H, W]
    float* sT = (float*)dyn;                  // reuse B region: [32][68]
    int b   = n0 / HWc;
    int hw0 = n0 % HWc;
    int tok0 = tg * 16 + (lane >> 2);
    for (int sg_it = 0; sg_it < 4; sg_it++) {
        for (int dc = 0; dc < 4; dc++) {
            if (sgp == sg_it) {
#pragma unroll
                for (int jj = 0; jj < 4; jj++) {
                    int j  = dc * 4 + jj;
                    int dl = jj * 8 + (lane & 3) * 2;
                    sT[dl * 68 + tok0]           = acc[j][0];
                    sT[(dl + 1) * 68 + tok0]     = acc[j][1];
                    sT[dl * 68 + tok0 + 8]       = acc[j][2];
                    sT[(dl + 1) * 68 + tok0 + 8] = acc[j][3];
                }
            }
            __syncthreads();
            {
                int dl  = tid >> 4;
                int hwl = (tid & 15) * 4;
                int d   = sg_it * 128 + dc * 32 + dl;
                float4 v = make_float4(sT[dl * 68 + hwl],     sT[dl * 68 + hwl + 1],
                                       sT[dl * 68 + hwl + 2], sT[dl * 68 + hwl + 3]);
                *(float4*)&out_upd[((size_t)(b * Dd + d)) * HWc + hw0 + hwl] = v;
            }
            __syncthreads();
        }
    }
}

// ---------------------------------------------------------------------------
extern "C" void kernel_launch(void* const* d_in, const int* in_sizes, int n_in,
                              void* d_out, int out_size) {
    const float* x    = (const float*)d_in[0];   // query_source [8,512,96,144]
    const float* pmem = (const float*)d_in[1];   // memory [512,512]
    float* out = (float*)d_out;

    const size_t ND = (size_t)Ntok * Dd;         // 56,623,104
    float* out_upd = out;                        // [B, D, H, W]
    float* out_sq  = out + ND;                   // softmax over tokens [N, M]
    float* out_sm  = out + 2 * ND;               // softmax over slots  [N, M]

    // Idempotent, capture-safe; needed for >48KB dynamic smem
    cudaFuncSetAttribute(k_g1, cudaFuncAttributeMaxDynamicSharedMemorySize, G1_SMEM);
    cudaFuncSetAttribute(k_g2, cudaFuncAttributeMaxDynamicSharedMemorySize, G2_SMEM);

    k_norm<<<Ntok / 256, 256>>>(x);
    k_prep<<<(Mm * Dd) / 256, 256>>>(pmem);
    k_qt<<<dim3(HWc / 32, Dd / 32, Bc), dim3(32, 8)>>>(x);
    k_g1<<<Ntok / 64, 512, G1_SMEM>>>(out_sq);
    k_sums<<<Ntok / 64, 256>>>(out_sq);
    k_g2<<<Ntok / 64, 512, G2_SMEM>>>(out_sq, out_sm, out_upd);
    (void)in_sizes; (void)n_in; (void)out_size;
}

// round 15
// speedup vs baseline: 1.9946x; 1.4421x over previous
#include <cuda_runtime.h>
#include <cuda_fp16.h>
#include <math.h>
#include <cstdint>

// Problem dims (fixed by the dataset)
#define Bc   8
#define Cc   512
#define Hc   96
#define Wc   144
#define HWc  (Hc * Wc)          // 13824
#define Ntok (Bc * HWc)         // 110592
#define Dd   512
#define Mm   512

// ---- k_g1 smem: BK=32 (2 sub-panels of 16k), double buffered, fp16 ----
// B panel (16k): 2p x 512 rows x 16B = 16384 B; 4 panels (buf*2+sub)
// A panel (16k): 2p x  64 rows x 16B =  2048 B; 4 panels
#define G1_OFF_B  0
#define G1_OFF_A  65536
#define G1_SMEM   73728

// ---- k_g2 smem: BK=16 double buffered, fp16 ----
#define G2_OFF_B     0
#define G2_OFF_A     32768
#define G2_OFF_CINV  36864
#define G2_OFF_RSINV 38912
#define G2_SMEM      39168

#define CP_ASYNC16(dst, src) \
    asm volatile("cp.async.ca.shared.global [%0], [%1], 16;" :: "r"(dst), "l"(src))
#define CP_COMMIT()  asm volatile("cp.async.commit_group;" ::: "memory")
#define CP_WAIT0()   asm volatile("cp.async.wait_group 0;" ::: "memory")

#define LDMX4(r, addr) \
    asm volatile("ldmatrix.sync.aligned.m8n8.x4.shared.b16 {%0,%1,%2,%3}, [%4];" \
        : "=r"((r)[0]), "=r"((r)[1]), "=r"((r)[2]), "=r"((r)[3]) : "r"(addr))

#define MMA16816(d, a, b0, b1) \
    asm volatile("mma.sync.aligned.m16n8k16.row.col.f32.f16.f16.f32 " \
        "{%0,%1,%2,%3}, {%4,%5,%6,%7}, {%8,%9}, {%0,%1,%2,%3};" \
        : "+f"((d)[0]), "+f"((d)[1]), "+f"((d)[2]), "+f"((d)[3]) \
        : "r"((a)[0]), "r"((a)[1]), "r"((a)[2]), "r"((a)[3]), "r"(b0), "r"(b1))

__device__ __forceinline__ uint32_t smem_u32(const void* p) {
    uint32_t a;
    asm("{ .reg .u64 t; cvta.to.shared.u64 t, %1; cvt.u32.u64 %0, t; }"
        : "=r"(a) : "l"(p));
    return a;
}

// Scratch (allocation-free rule: __device__ globals)
__device__ __half g_qh[(size_t)Ntok * Dd];     // normalized q, fp16 [N,D]
__device__ __half g_memh[Mm * Dd];             // mem fp16 [m][k]
__device__ __half g_memTh[Dd * Mm];            // mem fp16 transposed [d][m]
__device__ float g_inv[Ntok];
__device__ float g_rowsum[Ntok];
__device__ float g_colsum[Mm];

// ---------------------------------------------------------------------------
// K1: per-token inverse L2 norm over channels; zero colsum (replay idempotency)
// ---------------------------------------------------------------------------
__global__ void k_norm(const float* __restrict__ x) {
    int n = blockIdx.x * 256 + threadIdx.x;
    if (blockIdx.x == 0) {
        g_colsum[threadIdx.x]       = 0.0f;
        g_colsum[threadIdx.x + 256] = 0.0f;
    }
    if (n >= Ntok) return;
    int b = n / HWc, hw = n % HWc;
    const float* p = x + (size_t)b * Cc * HWc + hw;
    float s = 0.0f;
#pragma unroll 8
    for (int c = 0; c < Cc; c++) {
        float v = p[(size_t)c * HWc];
        s += v * v;
    }
    g_inv[n] = 1.0f / fmaxf(sqrtf(s), 1e-12f);
}

// ---------------------------------------------------------------------------
// K2: fp16 conversion of memory, [m][k] and transposed [d][m]
// ---------------------------------------------------------------------------
__global__ void k_prep(const float* __restrict__ pmem) {
    int idx = blockIdx.x * 256 + threadIdx.x;
    int m = idx >> 9, d = idx & 511;
    __half h = __float2half(pmem[idx]);
    g_memh[idx] = h;
    g_memTh[d * 512 + m] = h;
}

// ---------------------------------------------------------------------------
// K3: transpose+normalize q -> fp16 [N,D]
// ---------------------------------------------------------------------------
__global__ void k_qt(const float* __restrict__ x) {
    __shared__ float tile[32][33];
    int b   = blockIdx.z;
    int hw0 = blockIdx.x * 32;
    int d0  = blockIdx.y * 32;
    for (int r = threadIdx.y; r < 32; r += 8)
        tile[r][threadIdx.x] =
            x[((size_t)(b * Cc + d0 + r)) * HWc + hw0 + threadIdx.x];
    __syncthreads();
    for (int r = threadIdx.y; r < 32; r += 8) {
        int n = b * HWc + hw0 + r;
        g_qh[(size_t)n * Dd + d0 + threadIdx.x] =
            __float2half(tile[threadIdx.x][r] * g_inv[n]);
    }
}

// ---------------------------------------------------------------------------
// Staging (fp16): B panel = 512 rows x 16 k (32B/row), p-split at 8192
// ---------------------------------------------------------------------------
__device__ __forceinline__ void stage_B(uint32_t sb, uint32_t dstbase,
                                        const __half* __restrict__ B,
                                        int kc, int tid) {
#pragma unroll
    for (int it = 0; it < 2; it++) {
        int idx = tid + it * 512;          // 0..1023
        int n = idx & 511;
        int p = idx >> 9;
        const __half* src = B + (size_t)n * 512 + kc * 16 + p * 8;
        uint32_t dst = sb + dstbase + p * 8192 + n * 16;
        CP_ASYNC16(dst, src);
    }
}

__device__ __forceinline__ void stage_A1(uint32_t sb, uint32_t dstbase,
                                         const __half* __restrict__ A,
                                         int n0, int kc, int tid) {
    if (tid < 128) {
        int r = tid >> 1;
        int p = tid & 1;
        const __half* src = A + (size_t)(n0 + r) * 512 + kc * 16 + p * 8;
        uint32_t dst = sb + dstbase + p * 1024 + r * 16;
        CP_ASYNC16(dst, src);
    }
}

// A tile for gemm2: read raw E (f32), convert to fp16, and in passing emit
// out_sm = E*rinv, out_sq = E*cinv (each E element touched exactly once).
__device__ __forceinline__ void stage_A2(char* dyn, uint32_t dstbase,
                                         float* __restrict__ E,
                                         float* __restrict__ out_sm,
                                         const float* rs_inv, const float* cinv_s,
                                         int n0, int kc, int tid) {
    int r  = tid >> 3;
    int kk = (tid & 7) * 2;
    size_t off = (size_t)(n0 + r) * 512 + kc * 16 + kk;
    float2 e2 = *(const float2*)&E[off];
    float ri = rs_inv[r];
    *(float2*)&out_sm[off] = make_float2(e2.x * ri, e2.y * ri);
    int cgl = kc * 16 + kk;
    *(float2*)&E[off] = make_float2(e2.x * cinv_s[cgl], e2.y * cinv_s[cgl + 1]);
    int p = kk >> 3, c = kk & 7;
    *(__half2*)(dyn + dstbase + p * 1024 + r * 16 + c * 2) =
        __floats2half2_rn(e2.x, e2.y);
}

// ---------------------------------------------------------------------------
// k_g1 chunk: warp tile 32 tok x 64 slots (2 A + 4 B ldmatrix.x4, 16 mma)
// ---------------------------------------------------------------------------
__device__ __forceinline__ void g1_chunk(uint32_t bbase, uint32_t abase,
                                         int tg, int sgp, int lane,
                                         float acc[16][4]) {
    uint32_t ah[2][4];
#pragma unroll
    for (int mi = 0; mi < 2; mi++) {
        uint32_t a_addr = abase + (lane >> 4) * 1024
                        + (tg * 32 + mi * 16 + (lane & 15)) * 16;
        LDMX4(ah[mi], a_addr);
    }
    int g = lane >> 3;
    uint32_t b_base = bbase + (uint32_t)((g & 1) * 8192 + ((g >> 1) * 8 + (lane & 7)) * 16);
#pragma unroll
    for (int jp = 0; jp < 4; jp++) {
        uint32_t bh[4];
        LDMX4(bh, b_base + (uint32_t)((sgp * 64 + jp * 16) * 16));
#pragma unroll
        for (int mi = 0; mi < 2; mi++) {
            MMA16816(acc[mi * 8 + 2 * jp],     ah[mi], bh[0], bh[1]);
            MMA16816(acc[mi * 8 + 2 * jp + 1], ah[mi], bh[2], bh[3]);
        }
    }
}

// ---------------------------------------------------------------------------
// k_g2 chunk: warp tile 16 tok x 128 slots (1 A + 8 B ldmatrix.x4, 16 mma)
// ---------------------------------------------------------------------------
__device__ __forceinline__ void g2_chunk(uint32_t sb, int buf, int tg,
                                         int sgp, int lane,
                                         float acc[16][4]) {
    uint32_t ah[4];
    uint32_t a_addr = sb + G2_OFF_A + buf * 2048 + (lane >> 4) * 1024
                    + (tg * 16 + (lane & 15)) * 16;
    LDMX4(ah, a_addr);

    int g = lane >> 3;
    uint32_t b_base = sb + G2_OFF_B + buf * 16384
                    + (uint32_t)((g & 1) * 8192 + ((g >> 1) * 8 + (lane & 7)) * 16);
#pragma unroll
    for (int jp = 0; jp < 8; jp++) {
        uint32_t bh[4];
        LDMX4(bh, b_base + (uint32_t)((sgp * 128 + jp * 16) * 16));
        MMA16816(acc[2 * jp],     ah, bh[0], bh[1]);
        MMA16816(acc[2 * jp + 1], ah, bh[2], bh[3]);
    }
}

// ---------------------------------------------------------------------------
// K4: GEMM1 -> out_sq = E = exp(q . mem^T)  (raw).  BK=32 per barrier.
// ---------------------------------------------------------------------------
__global__ void __launch_bounds__(512, 1)
k_g1(float* __restrict__ out_sq) {
    extern __shared__ char dyn[];
    uint32_t sb = smem_u32(dyn);
    int tid = threadIdx.x, lane = tid & 31, wid = tid >> 5;
    int tg = wid & 1, sgp = wid >> 1;
    int n0 = blockIdx.x * 64;

    float acc[16][4];
#pragma unroll
    for (int j = 0; j < 16; j++)
#pragma unroll
        for (int q = 0; q < 4; q++) acc[j][q] = 0.0f;

    stage_B(sb, G1_OFF_B + 0 * 16384, g_memh, 0, tid);
    stage_B(sb, G1_OFF_B + 1 * 16384, g_memh, 1, tid);
    stage_A1(sb, G1_OFF_A + 0 * 2048, g_qh, n0, 0, tid);
    stage_A1(sb, G1_OFF_A + 1 * 2048, g_qh, n0, 1, tid);
    CP_COMMIT(); CP_WAIT0(); __syncthreads();

    int buf = 0;
    for (int kc32 = 0; kc32 < 16; kc32++) {
        if (kc32 < 15) {
            int nb = buf ^ 1;
            int kc = (kc32 + 1) * 2;
            stage_B(sb, G1_OFF_B + (nb * 2 + 0) * 16384, g_memh, kc, tid);
            stage_B(sb, G1_OFF_B + (nb * 2 + 1) * 16384, g_memh, kc + 1, tid);
            stage_A1(sb, G1_OFF_A + (nb * 2 + 0) * 2048, g_qh, n0, kc, tid);
            stage_A1(sb, G1_OFF_A + (nb * 2 + 1) * 2048, g_qh, n0, kc + 1, tid);
            CP_COMMIT();
        }
        g1_chunk(sb + G1_OFF_B + (buf * 2 + 0) * 16384,
                 sb + G1_OFF_A + (buf * 2 + 0) * 2048, tg, sgp, lane, acc);
        g1_chunk(sb + G1_OFF_B + (buf * 2 + 1) * 16384,
                 sb + G1_OFF_A + (buf * 2 + 1) * 2048, tg, sgp, lane, acc);
        if (kc32 < 15) CP_WAIT0();
        __syncthreads();
        buf ^= 1;
    }

    // epilogue: E = exp(score) (|score|<=1: no max-sub)
    int row0 = n0 + tg * 32 + (lane >> 2);
#pragma unroll
    for (int mi = 0; mi < 2; mi++)
#pragma unroll
        for (int j = 0; j < 8; j++) {
            int col = sgp * 64 + j * 8 + (lane & 3) * 2;
            const float* a = acc[mi * 8 + j];
            *(float2*)&out_sq[(size_t)(row0 + mi * 16) * 512 + col] =
                make_float2(__expf(a[0]), __expf(a[1]));
            *(float2*)&out_sq[(size_t)(row0 + mi * 16 + 8) * 512 + col] =
                make_float2(__expf(a[2]), __expf(a[3]));
        }
}

// ---------------------------------------------------------------------------
// K5: stream E once -> per-token rowsums (exact) + colsum atomics
// ---------------------------------------------------------------------------
__global__ void __launch_bounds__(256)
k_sums(const float* __restrict__ E) {
    __shared__ float rp[64];
    int tid = threadIdx.x, lane = tid & 31, w = tid >> 5;
    int n0 = blockIdx.x * 64;
    if (tid < 64) rp[tid] = 0.0f;
    __syncthreads();

    int c0 = w * 64 + lane * 2;
    float cs0 = 0.0f, cs1 = 0.0f;
    for (int t = 0; t < 64; t++) {
        float2 v = *(const float2*)&E[(size_t)(n0 + t) * 512 + c0];
        cs0 += v.x; cs1 += v.y;
        float s = v.x + v.y;
#pragma unroll
        for (int off = 16; off; off >>= 1)
            s += __shfl_xor_sync(0xFFFFFFFFu, s, off);
        if (lane == 0) atomicAdd(&rp[t], s);
    }
    __syncthreads();
    if (tid < 64) g_rowsum[n0 + tid] = rp[tid];
    atomicAdd(&g_colsum[c0],     cs0);
    atomicAdd(&g_colsum[c0 + 1], cs1);
}

// ---------------------------------------------------------------------------
// K6: GEMM2 upd = (E*rinv) . mem, fused score finalization in A-staging.
// ---------------------------------------------------------------------------
__global__ void __launch_bounds__(512, 1)
k_g2(float* __restrict__ out_sq,       // raw E in, E*cinv out
     float* __restrict__ out_sm,
     float* __restrict__ out_upd) {
    extern __shared__ char dyn[];
    uint32_t sb = smem_u32(dyn);
    float* cinv_s = (float*)(dyn + G2_OFF_CINV);
    float* rs_inv = (float*)(dyn + G2_OFF_RSINV);
    int tid = threadIdx.x, lane = tid & 31, wid = tid >> 5;
    int tg = wid & 3, sgp = wid >> 2;
    int n0 = blockIdx.x * 64;

    cinv_s[tid] = 1.0f / g_colsum[tid];
    if (tid < 64) rs_inv[tid] = 1.0f / g_rowsum[n0 + tid];
    __syncthreads();

    float acc[16][4];
#pragma unroll
    for (int j = 0; j < 16; j++)
#pragma unroll
        for (int q = 0; q < 4; q++) acc[j][q] = 0.0f;

    stage_B(sb, G2_OFF_B, g_memTh, 0, tid);
    CP_COMMIT();
    stage_A2(dyn, G2_OFF_A, out_sq, out_sm, rs_inv, cinv_s, n0, 0, tid);
    CP_WAIT0(); __syncthreads();

    int buf = 0;
    for (int kc = 0; kc < 32; kc++) {
        if (kc < 31) {
            stage_B(sb, G2_OFF_B + (buf ^ 1) * 16384, g_memTh, kc + 1, tid);
            CP_COMMIT();
            stage_A2(dyn, G2_OFF_A + (buf ^ 1) * 2048, out_sq, out_sm,
                     rs_inv, cinv_s, n0, kc + 1, tid);
        }
        g2_chunk(sb, buf, tg, sgp, lane, acc);
        if (kc < 31) CP_WAIT0();
        __syncthreads();
        buf ^= 1;
    }

    // scale rows by rinv (upd = P.mem with P = E*rinv)
    {
        float r0 = rs_inv[tg * 16 + (lane >> 2)];
        float r1 = rs_inv[tg * 16 + (lane >> 2) + 8];
#pragma unroll
        for (int j = 0; j < 16; j++) {
            acc[j][0] *= r0; acc[j][1] *= r0;
            acc[j][2] *= r1; acc[j][3] *= r1;
        }
    }

    // transpose to [B, D, H, W]
    float* sT = (float*)dyn;                  // reuse B region: [32][68]
    int b   = n0 / HWc;
    int hw0 = n0 % HWc;
    int tok0 = tg * 16 + (lane >> 2);
    for (int sg_it = 0; sg_it < 4; sg_it++) {
        for (int dc = 0; dc < 4; dc++) {
            if (sgp == sg_it) {
#pragma unroll
                for (int jj = 0; jj < 4; jj++) {
                    int j  = dc * 4 + jj;
                    int dl = jj * 8 + (lane & 3) * 2;
                    sT[dl * 68 + tok0]           = acc[j][0];
                    sT[(dl + 1) * 68 + tok0]     = acc[j][1];
                    sT[dl * 68 + tok0 + 8]       = acc[j][2];
                    sT[(dl + 1) * 68 + tok0 + 8] = acc[j][3];
                }
            }
            __syncthreads();
            {
                int dl  = tid >> 4;
                int hwl = (tid & 15) * 4;
                int d   = sg_it * 128 + dc * 32 + dl;
                float4 v = make_float4(sT[dl * 68 + hwl],     sT[dl * 68 + hwl + 1],
                                       sT[dl * 68 + hwl + 2], sT[dl * 68 + hwl + 3]);
                *(float4*)&out_upd[((size_t)(b * Dd + d)) * HWc + hw0 + hwl] = v;
            }
            __syncthreads();
        }
    }
}

// ---------------------------------------------------------------------------
extern "C" void kernel_launch(void* const* d_in, const int* in_sizes, int n_in,
                              void* d_out, int out_size) {
    const float* x    = (const float*)d_in[0];   // query_source [8,512,96,144]
    const float* pmem = (const float*)d_in[1];   // memory [512,512]
    float* out = (float*)d_out;

    const size_t ND = (size_t)Ntok * Dd;         // 56,623,104
    float* out_upd = out;                        // [B, D, H, W]
    float* out_sq  = out + ND;                   // softmax over tokens [N, M]
    float* out_sm  = out + 2 * ND;               // softmax over slots  [N, M]

    // Idempotent, capture-safe; needed for >48KB dynamic smem
    cudaFuncSetAttribute(k_g1, cudaFuncAttributeMaxDynamicSharedMemorySize, G1_SMEM);
    cudaFuncSetAttribute(k_g2, cudaFuncAttributeMaxDynamicSharedMemorySize, G2_SMEM);

    k_norm<<<Ntok / 256, 256>>>(x);
    k_prep<<<(Mm * Dd) / 256, 256>>>(pmem);
    k_qt<<<dim3(HWc / 32, Dd / 32, Bc), dim3(32, 8)>>>(x);
    k_g1<<<Ntok / 64, 512, G1_SMEM>>>(out_sq);
    k_sums<<<Ntok / 64, 256>>>(out_sq);
    k_g2<<<Ntok / 64, 512, G2_SMEM>>>(out_sq, out_sm, out_upd);
    (void)in_sizes; (void)n_in; (void)out_size;
}

// round 16
// speedup vs baseline: 2.1743x; 1.0901x over previous
#include <cuda_runtime.h>
#include <cuda_fp16.h>
#include <math.h>
#include <cstdint>

// Problem dims (fixed by the dataset)
#define Bc   8
#define Cc   512
#define Hc   96
#define Wc   144
#define HWc  (Hc * Wc)          // 13824
#define Ntok (Bc * HWc)         // 110592
#define Dd   512
#define Mm   512

// ---- k_g1 smem: BK=32 (2 sub-panels of 16k), double buffered, fp16 ----
// B panel (16k): 2p x 256 rows x 16B = 8192 B; 4 panels (buf*2+sub)
// A panel (16k): 2p x 128 rows x 16B = 4096 B; 4 panels
#define G1_OFF_B  0
#define G1_OFF_A  32768
#define G1_SMEM   49152

// ---- k_g2 smem: BK=16 double buffered, fp16 (R15-exact) ----
#define G2_OFF_B     0
#define G2_OFF_A     32768
#define G2_OFF_CINV  36864
#define G2_OFF_RSINV 38912
#define G2_SMEM      39168

#define CP_ASYNC16(dst, src) \
    asm volatile("cp.async.ca.shared.global [%0], [%1], 16;" :: "r"(dst), "l"(src))
#define CP_COMMIT()  asm volatile("cp.async.commit_group;" ::: "memory")
#define CP_WAIT0()   asm volatile("cp.async.wait_group 0;" ::: "memory")

#define LDMX4(r, addr) \
    asm volatile("ldmatrix.sync.aligned.m8n8.x4.shared.b16 {%0,%1,%2,%3}, [%4];" \
        : "=r"((r)[0]), "=r"((r)[1]), "=r"((r)[2]), "=r"((r)[3]) : "r"(addr))

#define MMA16816(d, a, b0, b1) \
    asm volatile("mma.sync.aligned.m16n8k16.row.col.f32.f16.f16.f32 " \
        "{%0,%1,%2,%3}, {%4,%5,%6,%7}, {%8,%9}, {%0,%1,%2,%3};" \
        : "+f"((d)[0]), "+f"((d)[1]), "+f"((d)[2]), "+f"((d)[3]) \
        : "r"((a)[0]), "r"((a)[1]), "r"((a)[2]), "r"((a)[3]), "r"(b0), "r"(b1))

__device__ __forceinline__ uint32_t smem_u32(const void* p) {
    uint32_t a;
    asm("{ .reg .u64 t; cvta.to.shared.u64 t, %1; cvt.u32.u64 %0, t; }"
        : "=r"(a) : "l"(p));
    return a;
}

// Scratch (allocation-free rule: __device__ globals)
__device__ __half g_qh[(size_t)Ntok * Dd];     // normalized q, fp16 [N,D]
__device__ __half g_memh[Mm * Dd];             // mem fp16 [m][k]
__device__ __half g_memTh[Dd * Mm];            // mem fp16 transposed [d][m]
__device__ float g_inv[Ntok];
__device__ float g_rowsum[Ntok];
__device__ float g_colsum[Mm];

// ---------------------------------------------------------------------------
// K1: per-token inverse L2 norm over channels; zero colsum (replay idempotency)
// ---------------------------------------------------------------------------
__global__ void k_norm(const float* __restrict__ x) {
    int n = blockIdx.x * 256 + threadIdx.x;
    if (blockIdx.x == 0) {
        g_colsum[threadIdx.x]       = 0.0f;
        g_colsum[threadIdx.x + 256] = 0.0f;
    }
    if (n >= Ntok) return;
    int b = n / HWc, hw = n % HWc;
    const float* p = x + (size_t)b * Cc * HWc + hw;
    float s = 0.0f;
#pragma unroll 8
    for (int c = 0; c < Cc; c++) {
        float v = p[(size_t)c * HWc];
        s += v * v;
    }
    g_inv[n] = 1.0f / fmaxf(sqrtf(s), 1e-12f);
}

// ---------------------------------------------------------------------------
// K2: fp16 conversion of memory, [m][k] and transposed [d][m]
// ---------------------------------------------------------------------------
__global__ void k_prep(const float* __restrict__ pmem) {
    int idx = blockIdx.x * 256 + threadIdx.x;
    int m = idx >> 9, d = idx & 511;
    __half h = __float2half(pmem[idx]);
    g_memh[idx] = h;
    g_memTh[d * 512 + m] = h;
}

// ---------------------------------------------------------------------------
// K3: transpose+normalize q -> fp16 [N,D]
// ---------------------------------------------------------------------------
__global__ void k_qt(const float* __restrict__ x) {
    __shared__ float tile[32][33];
    int b   = blockIdx.z;
    int hw0 = blockIdx.x * 32;
    int d0  = blockIdx.y * 32;
    for (int r = threadIdx.y; r < 32; r += 8)
        tile[r][threadIdx.x] =
            x[((size_t)(b * Cc + d0 + r)) * HWc + hw0 + threadIdx.x];
    __syncthreads();
    for (int r = threadIdx.y; r < 32; r += 8) {
        int n = b * HWc + hw0 + r;
        g_qh[(size_t)n * Dd + d0 + threadIdx.x] =
            __float2half(tile[threadIdx.x][r] * g_inv[n]);
    }
}

// ---------------------------------------------------------------------------
// Staging helpers
// ---------------------------------------------------------------------------
// g1: B panel = 256 rows x 16 k, 256 threads, 2 cp.async each
__device__ __forceinline__ void stage_B256(uint32_t sb, uint32_t dstbase,
                                           const __half* __restrict__ B,
                                           int m0, int kc, int tid) {
#pragma unroll
    for (int it = 0; it < 2; it++) {
        int idx = tid + it * 256;          // 0..511
        int n = idx & 255;
        int p = idx >> 8;
        const __half* src = B + (size_t)(m0 + n) * 512 + kc * 16 + p * 8;
        uint32_t dst = sb + dstbase + p * 4096 + n * 16;
        CP_ASYNC16(dst, src);
    }
}

// g1: A panel = 128 rows x 16 k, 256 threads, 1 cp.async each
__device__ __forceinline__ void stage_A1(uint32_t sb, uint32_t dstbase,
                                         const __half* __restrict__ A,
                                         int n0, int kc, int tid) {
    int r = tid >> 1;
    int p = tid & 1;
    const __half* src = A + (size_t)(n0 + r) * 512 + kc * 16 + p * 8;
    uint32_t dst = sb + dstbase + p * 2048 + r * 16;
    CP_ASYNC16(dst, src);
}

// g2: B panel = 512 rows x 16 k, 512 threads (R15-exact)
__device__ __forceinline__ void stage_B(uint32_t sb, uint32_t dstbase,
                                        const __half* __restrict__ B,
                                        int kc, int tid) {
#pragma unroll
    for (int it = 0; it < 2; it++) {
        int idx = tid + it * 512;          // 0..1023
        int n = idx & 511;
        int p = idx >> 9;
        const __half* src = B + (size_t)n * 512 + kc * 16 + p * 8;
        uint32_t dst = sb + dstbase + p * 8192 + n * 16;
        CP_ASYNC16(dst, src);
    }
}

// A tile for gemm2: read raw E (f32), convert to fp16, and in passing emit
// out_sm = E*rinv, out_sq = E*cinv (each E element touched exactly once).
__device__ __forceinline__ void stage_A2(char* dyn, uint32_t dstbase,
                                         float* __restrict__ E,
                                         float* __restrict__ out_sm,
                                         const float* rs_inv, const float* cinv_s,
                                         int n0, int kc, int tid) {
    int r  = tid >> 3;
    int kk = (tid & 7) * 2;
    size_t off = (size_t)(n0 + r) * 512 + kc * 16 + kk;
    float2 e2 = *(const float2*)&E[off];
    float ri = rs_inv[r];
    *(float2*)&out_sm[off] = make_float2(e2.x * ri, e2.y * ri);
    int cgl = kc * 16 + kk;
    *(float2*)&E[off] = make_float2(e2.x * cinv_s[cgl], e2.y * cinv_s[cgl + 1]);
    int p = kk >> 3, c = kk & 7;
    *(__half2*)(dyn + dstbase + p * 1024 + r * 16 + c * 2) =
        __floats2half2_rn(e2.x, e2.y);
}

// ---------------------------------------------------------------------------
// k_g1 chunk: warp tile 64 tok x 64 slots (4 A + 4 B ldmatrix.x4, 32 mma)
// ---------------------------------------------------------------------------
__device__ __forceinline__ void g1_chunk(uint32_t bbase, uint32_t abase,
                                         int tg, int sgp, int lane,
                                         float acc[32][4]) {
    uint32_t ah[4][4];
#pragma unroll
    for (int mi = 0; mi < 4; mi++) {
        uint32_t a_addr = abase + (lane >> 4) * 2048
                        + (tg * 64 + mi * 16 + (lane & 15)) * 16;
        LDMX4(ah[mi], a_addr);
    }
    int g = lane >> 3;
    uint32_t b_base = bbase + (uint32_t)((g & 1) * 4096 + ((g >> 1) * 8 + (lane & 7)) * 16);
#pragma unroll
    for (int jp = 0; jp < 4; jp++) {
        uint32_t bh[4];
        LDMX4(bh, b_base + (uint32_t)((sgp * 64 + jp * 16) * 16));
#pragma unroll
        for (int mi = 0; mi < 4; mi++) {
            MMA16816(acc[mi * 8 + 2 * jp],     ah[mi], bh[0], bh[1]);
            MMA16816(acc[mi * 8 + 2 * jp + 1], ah[mi], bh[2], bh[3]);
        }
    }
}

// ---------------------------------------------------------------------------
// k_g2 chunk (R15-exact): warp tile 16 tok x 128 slots
// ---------------------------------------------------------------------------
__device__ __forceinline__ void g2_chunk(uint32_t sb, int buf, int tg,
                                         int sgp, int lane,
                                         float acc[16][4]) {
    uint32_t ah[4];
    uint32_t a_addr = sb + G2_OFF_A + buf * 2048 + (lane >> 4) * 1024
                    + (tg * 16 + (lane & 15)) * 16;
    LDMX4(ah, a_addr);

    int g = lane >> 3;
    uint32_t b_base = sb + G2_OFF_B + buf * 16384
                    + (uint32_t)((g & 1) * 8192 + ((g >> 1) * 8 + (lane & 7)) * 16);
#pragma unroll
    for (int jp = 0; jp < 8; jp++) {
        uint32_t bh[4];
        LDMX4(bh, b_base + (uint32_t)((sgp * 128 + jp * 16) * 16));
        MMA16816(acc[2 * jp],     ah, bh[0], bh[1]);
        MMA16816(acc[2 * jp + 1], ah, bh[2], bh[3]);
    }
}

// ---------------------------------------------------------------------------
// K4: GEMM1 -> out_sq = E = exp(q . mem^T)  (raw).
// CTA = 128 tok x 256 slots, 256 thr (8 warps: tg=wid&1, sgp=wid>>1).
// grid = (Ntok/128, 2): blockIdx.y selects the 256-slot half.
// ---------------------------------------------------------------------------
__global__ void __launch_bounds__(256, 1)
k_g1(float* __restrict__ out_sq) {
    extern __shared__ char dyn[];
    uint32_t sb = smem_u32(dyn);
    int tid = threadIdx.x, lane = tid & 31, wid = tid >> 5;
    int tg = wid & 1, sgp = wid >> 1;
    int n0 = blockIdx.x * 128;
    int m0 = blockIdx.y * 256;

    float acc[32][4];
#pragma unroll
    for (int j = 0; j < 32; j++)
#pragma unroll
        for (int q = 0; q < 4; q++) acc[j][q] = 0.0f;

    stage_B256(sb, G1_OFF_B + 0 * 8192, g_memh, m0, 0, tid);
    stage_B256(sb, G1_OFF_B + 1 * 8192, g_memh, m0, 1, tid);
    stage_A1(sb, G1_OFF_A + 0 * 4096, g_qh, n0, 0, tid);
    stage_A1(sb, G1_OFF_A + 1 * 4096, g_qh, n0, 1, tid);
    CP_COMMIT(); CP_WAIT0(); __syncthreads();

    int buf = 0;
    for (int kc32 = 0; kc32 < 16; kc32++) {
        if (kc32 < 15) {
            int nb = buf ^ 1;
            int kc = (kc32 + 1) * 2;
            stage_B256(sb, G1_OFF_B + (nb * 2 + 0) * 8192, g_memh, m0, kc, tid);
            stage_B256(sb, G1_OFF_B + (nb * 2 + 1) * 8192, g_memh, m0, kc + 1, tid);
            stage_A1(sb, G1_OFF_A + (nb * 2 + 0) * 4096, g_qh, n0, kc, tid);
            stage_A1(sb, G1_OFF_A + (nb * 2 + 1) * 4096, g_qh, n0, kc + 1, tid);
            CP_COMMIT();
        }
        g1_chunk(sb + G1_OFF_B + (buf * 2 + 0) * 8192,
                 sb + G1_OFF_A + (buf * 2 + 0) * 4096, tg, sgp, lane, acc);
        g1_chunk(sb + G1_OFF_B + (buf * 2 + 1) * 8192,
                 sb + G1_OFF_A + (buf * 2 + 1) * 4096, tg, sgp, lane, acc);
        if (kc32 < 15) CP_WAIT0();
        __syncthreads();
        buf ^= 1;
    }

    // epilogue: E = exp(score) (|score|<=1: no max-sub)
#pragma unroll
    for (int mi = 0; mi < 4; mi++) {
        int row0 = n0 + tg * 64 + mi * 16 + (lane >> 2);
#pragma unroll
        for (int j = 0; j < 8; j++) {
            int col = m0 + sgp * 64 + j * 8 + (lane & 3) * 2;
            const float* a = acc[mi * 8 + j];
            *(float2*)&out_sq[(size_t)row0 * 512 + col] =
                make_float2(__expf(a[0]), __expf(a[1]));
            *(float2*)&out_sq[(size_t)(row0 + 8) * 512 + col] =
                make_float2(__expf(a[2]), __expf(a[3]));
        }
    }
}

// ---------------------------------------------------------------------------
// K5: stream E once -> per-token rowsums (exact) + colsum atomics
// ---------------------------------------------------------------------------
__global__ void __launch_bounds__(256)
k_sums(const float* __restrict__ E) {
    __shared__ float rp[64];
    int tid = threadIdx.x, lane = tid & 31, w = tid >> 5;
    int n0 = blockIdx.x * 64;
    if (tid < 64) rp[tid] = 0.0f;
    __syncthreads();

    int c0 = w * 64 + lane * 2;
    float cs0 = 0.0f, cs1 = 0.0f;
    for (int t = 0; t < 64; t++) {
        float2 v = *(const float2*)&E[(size_t)(n0 + t) * 512 + c0];
        cs0 += v.x; cs1 += v.y;
        float s = v.x + v.y;
#pragma unroll
        for (int off = 16; off; off >>= 1)
            s += __shfl_xor_sync(0xFFFFFFFFu, s, off);
        if (lane == 0) atomicAdd(&rp[t], s);
    }
    __syncthreads();
    if (tid < 64) g_rowsum[n0 + tid] = rp[tid];
    atomicAdd(&g_colsum[c0],     cs0);
    atomicAdd(&g_colsum[c0 + 1], cs1);
}

// ---------------------------------------------------------------------------
// K6: GEMM2 upd = (E*rinv) . mem, fused score finalization in A-staging.
// (R15-exact)
// ---------------------------------------------------------------------------
__global__ void __launch_bounds__(512, 1)
k_g2(float* __restrict__ out_sq,       // raw E in, E*cinv out
     float* __restrict__ out_sm,
     float* __restrict__ out_upd) {
    extern __shared__ char dyn[];
    uint32_t sb = smem_u32(dyn);
    float* cinv_s = (float*)(dyn + G2_OFF_CINV);
    float* rs_inv = (float*)(dyn + G2_OFF_RSINV);
    int tid = threadIdx.x, lane = tid & 31, wid = tid >> 5;
    int tg = wid & 3, sgp = wid >> 2;
    int n0 = blockIdx.x * 64;

    cinv_s[tid] = 1.0f / g_colsum[tid];
    if (tid < 64) rs_inv[tid] = 1.0f / g_rowsum[n0 + tid];
    __syncthreads();

    float acc[16][4];
#pragma unroll
    for (int j = 0; j < 16; j++)
#pragma unroll
        for (int q = 0; q < 4; q++) acc[j][q] = 0.0f;

    stage_B(sb, G2_OFF_B, g_memTh, 0, tid);
    CP_COMMIT();
    stage_A2(dyn, G2_OFF_A, out_sq, out_sm, rs_inv, cinv_s, n0, 0, tid);
    CP_WAIT0(); __syncthreads();

    int buf = 0;
    for (int kc = 0; kc < 32; kc++) {
        if (kc < 31) {
            stage_B(sb, G2_OFF_B + (buf ^ 1) * 16384, g_memTh, kc + 1, tid);
            CP_COMMIT();
            stage_A2(dyn, G2_OFF_A + (buf ^ 1) * 2048, out_sq, out_sm,
                     rs_inv, cinv_s, n0, kc + 1, tid);
        }
        g2_chunk(sb, buf, tg, sgp, lane, acc);
        if (kc < 31) CP_WAIT0();
        __syncthreads();
        buf ^= 1;
    }

    // scale rows by rinv (upd = P.mem with P = E*rinv)
    {
        float r0 = rs_inv[tg * 16 + (lane >> 2)];
        float r1 = rs_inv[tg * 16 + (lane >> 2) + 8];
#pragma unroll
        for (int j = 0; j < 16; j++) {
            acc[j][0] *= r0; acc[j][1] *= r0;
            acc[j][2] *= r1; acc[j][3] *= r1;
        }
    }

    // transpose to [B, D, H, W]
    float* sT = (float*)dyn;                  // reuse B region: [32][68]
    int b   = n0 / HWc;
    int hw0 = n0 % HWc;
    int tok0 = tg * 16 + (lane >> 2);
    for (int sg_it = 0; sg_it < 4; sg_it++) {
        for (int dc = 0; dc < 4; dc++) {
            if (sgp == sg_it) {
#pragma unroll
                for (int jj = 0; jj < 4; jj++) {
                    int j  = dc * 4 + jj;
                    int dl = jj * 8 + (lane & 3) * 2;
                    sT[dl * 68 + tok0]           = acc[j][0];
                    sT[(dl + 1) * 68 + tok0]     = acc[j][1];
                    sT[dl * 68 + tok0 + 8]       = acc[j][2];
                    sT[(dl + 1) * 68 + tok0 + 8] = acc[j][3];
                }
            }
            __syncthreads();
            {
                int dl  = tid >> 4;
                int hwl = (tid & 15) * 4;
                int d   = sg_it * 128 + dc * 32 + dl;
                float4 v = make_float4(sT[dl * 68 + hwl],     sT[dl * 68 + hwl + 1],
                                       sT[dl * 68 + hwl + 2], sT[dl * 68 + hwl + 3]);
                *(float4*)&out_upd[((size_t)(b * Dd + d)) * HWc + hw0 + hwl] = v;
            }
            __syncthreads();
        }
    }
}

// ---------------------------------------------------------------------------
extern "C" void kernel_launch(void* const* d_in, const int* in_sizes, int n_in,
                              void* d_out, int out_size) {
    const float* x    = (const float*)d_in[0];   // query_source [8,512,96,144]
    const float* pmem = (const float*)d_in[1];   // memory [512,512]
    float* out = (float*)d_out;

    const size_t ND = (size_t)Ntok * Dd;         // 56,623,104
    float* out_upd = out;                        // [B, D, H, W]
    float* out_sq  = out + ND;                   // softmax over tokens [N, M]
    float* out_sm  = out + 2 * ND;               // softmax over slots  [N, M]

    // Idempotent, capture-safe; needed for >48KB dynamic smem
    cudaFuncSetAttribute(k_g1, cudaFuncAttributeMaxDynamicSharedMemorySize, G1_SMEM);
    cudaFuncSetAttribute(k_g2, cudaFuncAttributeMaxDynamicSharedMemorySize, G2_SMEM);

    k_norm<<<Ntok / 256, 256>>>(x);
    k_prep<<<(Mm * Dd) / 256, 256>>>(pmem);
    k_qt<<<dim3(HWc / 32, Dd / 32, Bc), dim3(32, 8)>>>(x);
    k_g1<<<dim3(Ntok / 128, 2), 256, G1_SMEM>>>(out_sq);
    k_sums<<<Ntok / 64, 256>>>(out_sq);
    k_g2<<<Ntok / 64, 512, G2_SMEM>>>(out_sq, out_sm, out_upd);
    (void)in_sizes; (void)n_in; (void)out_size;
}